// round 10
// baseline (speedup 1.0000x reference)
#include <cuda_runtime.h>

#define GEPS    1e-7f
#define GACLIP  (1.0f - 1e-6f)
#define GPI     3.14159274101257324f   /* float32(np.pi) */
#define GPIH    1.57079637050628662f   /* pi/2 */

// Single-MUFU approximate sqrt (rel err ~2^-21; error budget is 1e-3).
__device__ __forceinline__ float fsqrt_approx(float x)
{
    float r;
    asm("sqrt.approx.f32 %0, %1;" : "=f"(r) : "f"(x));
    return r;
}

__device__ __forceinline__ float frcp_approx(float x)
{
    float r;
    asm("rcp.approx.f32 %0, %1;" : "=f"(r) : "f"(x));
    return r;
}

// Abramowitz-Stegun 4.4.45 core: acos(xa) for xa in [0, ACLIP].
__device__ __forceinline__ float acos_core(float xa)
{
    float p = fmaf(-0.0187293f, xa, 0.0742610f);
    p = fmaf(p, xa, -0.2121144f);
    p = fmaf(p, xa, 1.5707288f);
    return fsqrt_approx(1.0f - xa) * p;
}

// acos with sign reflection via copysign (no predicate chain):
// acos(v) = pi/2 - copysign(pi/2 - acos(|v|), v)
__device__ __forceinline__ float acos_signed(float v)
{
    float ac = acos_core(fminf(fabsf(v), GACLIP));
    return GPIH - copysignf(GPIH - ac, v);
}

// Branchless circle GIoU loss; EPS/ACLIP clamps reproduce the reference's
// lens/contained/disjoint branches to ~2e-4 absolute per element.
__device__ __forceinline__ float circle_giou_loss(
    float cx0, float cy0, float r0,
    float cx1, float cy1, float r1)
{
    float dx = cx0 - cx1;
    float dy = cy0 - cy1;
    float d2  = fmaf(dx, dx, dy * dy);
    float rinv = rsqrtf(d2);           // 1/d

    float s    = r0 + r1;
    float rd   = r0 - r1;
    float r0sq = r0 * r0;
    float r1sq = r1 * r1;
    float s2     = s * s;
    float rdiff2 = rd * rd;
    float dr2    = r0sq - r1sq;

    // cos_k = (d2 +- dr2)/(2 d rk). One reciprocal serves both:
    // 1/r0 = r1*rcp(r0 r1), 1/r1 = r0*rcp(r0 r1).
    float pre = frcp_approx(r0 * r1) * (0.5f * rinv);
    float v0 = (d2 + dr2) * (r1 * pre);
    float v1 = (d2 - dr2) * (r0 * pre);

    float a0 = acos_signed(v0);
    float a1 = acos_signed(v1);

    // sqrt(t) factored: st = sqrt(s2-d2) * sqrt(d2-rdiff2), each clamped.
    float hb  = d2 - rdiff2;
    float sh  = fsqrt_approx(fmaxf(hb, GEPS));          // also the hull term
    float st  = fsqrt_approx(fmaxf(s2 - d2, GEPS)) * sh;

    float inter = fmaf(r0sq, a0, fmaf(r1sq, a1, -0.5f * st));
    float uni   = fmaf(GPI, r0sq + r1sq, -inter);

    float q = fminf(fabsf(rd) * rinv, GACLIP);
    float alpha = acos_core(q);

    // hull = pi*rmax^2 - alpha*(rmax^2 - rmin^2) + s*sqrt(h2)
    float rmaxsq = fmaxf(r0sq, r1sq);
    float hull = fmaf(GPI, rmaxsq, fmaf(-alpha, fabsf(dr2), s * sh));

    // loss = 2 - inter/uni - uni/hull, via a single reciprocal of uni*hull.
    float rcpuh = frcp_approx(uni * hull);
    float iou   = inter * hull * rcpuh;
    float uoh   = uni * uni * rcpuh;
    return (2.0f - iou) - uoh;
}

// Single-kernel reduction scratch (allocation-free: __device__ globals).
// g_counter starts 0 and is reset by the last block every launch, so every
// graph replay sees identical initial state (deterministic).
__device__ float    g_partials[2048];
__device__ unsigned g_counter = 0;

__global__ __launch_bounds__(256, 3)   // 85-reg budget: R8's winning shape
void giou_kernel(const float4* __restrict__ x4,
                 const float4* __restrict__ y4,
                 float* __restrict__ out,
                 int nblocks)
{
    const unsigned tid = blockIdx.x * blockDim.x + threadIdx.x;

    // All 12 float4 loads batched up front (MLP=12) — R8's winning pattern.
    const unsigned base = 6u * tid;
    float4 xa = x4[base + 0], xb = x4[base + 1], xc = x4[base + 2];
    float4 xd = x4[base + 3], xe = x4[base + 4], xf = x4[base + 5];
    float4 ya = y4[base + 0], yb = y4[base + 1], yc = y4[base + 2];
    float4 yd = y4[base + 3], ye = y4[base + 4], yf = y4[base + 5];

    float acc0, acc1;
    acc0  = circle_giou_loss(xa.x, xa.y, xa.z,  ya.x, ya.y, ya.z);
    acc1  = circle_giou_loss(xa.w, xb.x, xb.y,  ya.w, yb.x, yb.y);
    acc0 += circle_giou_loss(xb.z, xb.w, xc.x,  yb.z, yb.w, yc.x);
    acc1 += circle_giou_loss(xc.y, xc.z, xc.w,  yc.y, yc.z, yc.w);
    acc0 += circle_giou_loss(xd.x, xd.y, xd.z,  yd.x, yd.y, yd.z);
    acc1 += circle_giou_loss(xd.w, xe.x, xe.y,  yd.w, ye.x, ye.y);
    acc0 += circle_giou_loss(xe.z, xe.w, xf.x,  ye.z, ye.w, yf.x);
    acc1 += circle_giou_loss(xf.y, xf.z, xf.w,  yf.y, yf.z, yf.w);
    float acc = acc0 + acc1;

    // Warp reduce
    #pragma unroll
    for (int off = 16; off > 0; off >>= 1)
        acc += __shfl_down_sync(0xffffffffu, acc, off);

    __shared__ float warp_sums[8];
    __shared__ bool  s_is_last;
    const int lane = threadIdx.x & 31;
    const int warp = threadIdx.x >> 5;
    if (lane == 0) warp_sums[warp] = acc;
    __syncthreads();

    // Publish block partial; last-arriving block reduces all partials.
    if (threadIdx.x == 0) {
        float bsum = warp_sums[0] + warp_sums[1] + warp_sums[2] + warp_sums[3]
                   + warp_sums[4] + warp_sums[5] + warp_sums[6] + warp_sums[7];
        g_partials[blockIdx.x] = bsum;
        __threadfence();
        unsigned prev = atomicAdd(&g_counter, 1u);
        s_is_last = (prev == (unsigned)(nblocks - 1));
    }
    __syncthreads();

    if (s_is_last) {
        float v = 0.0f;
        for (int i = threadIdx.x; i < nblocks; i += 256)
            v += ((volatile float*)g_partials)[i];

        #pragma unroll
        for (int off = 16; off > 0; off >>= 1)
            v += __shfl_down_sync(0xffffffffu, v, off);

        if (lane == 0) warp_sums[warp] = v;
        __syncthreads();

        if (threadIdx.x == 0) {
            float total = warp_sums[0] + warp_sums[1] + warp_sums[2] + warp_sums[3]
                        + warp_sums[4] + warp_sums[5] + warp_sums[6] + warp_sums[7];
            *out = total;
            g_counter = 0;             // reset for the next (replayed) launch
        }
    }
}

extern "C" void kernel_launch(void* const* d_in, const int* in_sizes, int n_in,
                              void* d_out, int out_size)
{
    const float4* x4 = (const float4*)d_in[0];
    const float4* y4 = (const float4*)d_in[1];
    float* out = (float*)d_out;

    const int n_rows = in_sizes[0] / 3;          // 4194304
    const int threads = 256;
    const int rows_per_block = threads * 8;      // 2048
    const int blocks = (n_rows + rows_per_block - 1) / rows_per_block;  // 2048

    giou_kernel<<<blocks, threads>>>(x4, y4, out, blocks);
}

// round 11
// speedup vs baseline: 1.1180x; 1.1180x over previous
#include <cuda_runtime.h>

#define GEPS    1e-7f
#define GACLIP  (1.0f - 1e-6f)
#define GPI     3.14159274101257324f   /* float32(np.pi) */
#define GPIH    1.57079637050628662f   /* pi/2 */

// Single-MUFU approximate sqrt (rel err ~2^-21; error budget is 1e-3).
__device__ __forceinline__ float fsqrt_approx(float x)
{
    float r;
    asm("sqrt.approx.f32 %0, %1;" : "=f"(r) : "f"(x));
    return r;
}

__device__ __forceinline__ float frcp_approx(float x)
{
    float r;
    asm("rcp.approx.f32 %0, %1;" : "=f"(r) : "f"(x));
    return r;
}

// Abramowitz-Stegun 4.4.45 core: acos(xa) for xa in [0, ACLIP].
__device__ __forceinline__ float acos_core(float xa)
{
    float p = fmaf(-0.0187293f, xa, 0.0742610f);
    p = fmaf(p, xa, -0.2121144f);
    p = fmaf(p, xa, 1.5707288f);
    return fsqrt_approx(1.0f - xa) * p;
}

// acos with sign reflection via copysign (no predicate chain):
// acos(v) = pi/2 - copysign(pi/2 - acos(|v|), v)
__device__ __forceinline__ float acos_signed(float v)
{
    float ac = acos_core(fminf(fabsf(v), GACLIP));
    return GPIH - copysignf(GPIH - ac, v);
}

// Branchless circle GIoU loss; EPS/ACLIP clamps reproduce the reference's
// lens/contained/disjoint branches to ~2e-4 absolute per element.
__device__ __forceinline__ float circle_giou_loss(
    float cx0, float cy0, float r0,
    float cx1, float cy1, float r1)
{
    float dx = cx0 - cx1;
    float dy = cy0 - cy1;
    float d2  = fmaf(dx, dx, dy * dy);

    float s    = r0 + r1;
    float rd   = r0 - r1;
    float r0sq = r0 * r0;
    float r1sq = r1 * r1;
    float s2     = s * s;
    float rdiff2 = rd * rd;
    float dr2    = r0sq - r1sq;

    // One MUFU serves 1/d, 1/(d r0), 1/(d r1):
    //   spre = rsqrt(d2 * (r0 r1)^2) = 1/(d r0 r1)
    //   1/(d r0) = r1 * spre ; 1/(d r1) = r0 * spre ; 1/d = r0 r1 * spre
    float r01   = r0 * r1;
    float spre  = rsqrtf(d2 * (r01 * r01));
    float hpre  = 0.5f * spre;
    float rinv  = r01 * spre;          // 1/d

    float v0 = (d2 + dr2) * (r1 * hpre);
    float v1 = (d2 - dr2) * (r0 * hpre);

    float a0 = acos_signed(v0);
    float a1 = acos_signed(v1);

    // sqrt(t) factored: st = sqrt(s2-d2) * sqrt(d2-rdiff2), each clamped.
    float hb  = d2 - rdiff2;
    float sh  = fsqrt_approx(fmaxf(hb, GEPS));          // also the hull term
    float st  = fsqrt_approx(fmaxf(s2 - d2, GEPS)) * sh;

    float inter = fmaf(r0sq, a0, fmaf(r1sq, a1, -0.5f * st));
    float uni   = fmaf(GPI, r0sq + r1sq, -inter);

    float q = fminf(fabsf(rd) * rinv, GACLIP);
    float alpha = acos_core(q);

    // hull = pi*rmax^2 - alpha*(rmax^2 - rmin^2) + s*sqrt(h2)
    float rmaxsq = fmaxf(r0sq, r1sq);
    float hull = fmaf(GPI, rmaxsq, fmaf(-alpha, fabsf(dr2), s * sh));

    // loss = 2 - inter/uni - uni/hull, via a single reciprocal of uni*hull.
    float rcpuh = frcp_approx(uni * hull);
    float iou   = inter * hull * rcpuh;
    float uoh   = uni * uni * rcpuh;
    return (2.0f - iou) - uoh;
}

__global__ void giou_zero_kernel(float* __restrict__ out)
{
    *out = 0.0f;
}

__global__ __launch_bounds__(256, 3)   // 85-reg budget: R8's winning shape
void giou_kernel(const float4* __restrict__ x4,
                 const float4* __restrict__ y4,
                 float* __restrict__ out)
{
    const unsigned tid = blockIdx.x * blockDim.x + threadIdx.x;

    // All 12 float4 loads batched up front (MLP=12) — the proven pattern.
    const unsigned base = 6u * tid;
    float4 xa = x4[base + 0], xb = x4[base + 1], xc = x4[base + 2];
    float4 xd = x4[base + 3], xe = x4[base + 4], xf = x4[base + 5];
    float4 ya = y4[base + 0], yb = y4[base + 1], yc = y4[base + 2];
    float4 yd = y4[base + 3], ye = y4[base + 4], yf = y4[base + 5];

    float acc0, acc1;
    acc0  = circle_giou_loss(xa.x, xa.y, xa.z,  ya.x, ya.y, ya.z);
    acc1  = circle_giou_loss(xa.w, xb.x, xb.y,  ya.w, yb.x, yb.y);
    acc0 += circle_giou_loss(xb.z, xb.w, xc.x,  yb.z, yb.w, yc.x);
    acc1 += circle_giou_loss(xc.y, xc.z, xc.w,  yc.y, yc.z, yc.w);
    acc0 += circle_giou_loss(xd.x, xd.y, xd.z,  yd.x, yd.y, yd.z);
    acc1 += circle_giou_loss(xd.w, xe.x, xe.y,  yd.w, ye.x, ye.y);
    acc0 += circle_giou_loss(xe.z, xe.w, xf.x,  ye.z, ye.w, yf.x);
    acc1 += circle_giou_loss(xf.y, xf.z, xf.w,  yf.y, yf.z, yf.w);
    float acc = acc0 + acc1;

    // Warp reduce
    #pragma unroll
    for (int off = 16; off > 0; off >>= 1)
        acc += __shfl_down_sync(0xffffffffu, acc, off);

    __shared__ float warp_sums[8];
    const int lane = threadIdx.x & 31;
    const int warp = threadIdx.x >> 5;
    if (lane == 0) warp_sums[warp] = acc;
    __syncthreads();

    if (threadIdx.x < 8) {
        float v = warp_sums[threadIdx.x];
        #pragma unroll
        for (int off = 4; off > 0; off >>= 1)
            v += __shfl_down_sync(0xffu, v, off);
        if (threadIdx.x == 0)
            atomicAdd(out, v);
    }
}

extern "C" void kernel_launch(void* const* d_in, const int* in_sizes, int n_in,
                              void* d_out, int out_size)
{
    const float4* x4 = (const float4*)d_in[0];
    const float4* y4 = (const float4*)d_in[1];
    float* out = (float*)d_out;

    const int n_rows = in_sizes[0] / 3;          // 4194304
    const int threads = 256;
    const int rows_per_block = threads * 8;      // 2048
    const int blocks = (n_rows + rows_per_block - 1) / rows_per_block;  // 2048

    giou_zero_kernel<<<1, 1>>>(out);
    giou_kernel<<<blocks, threads>>>(x4, y4, out);
}